// round 1
// baseline (speedup 1.0000x reference)
#include <cuda_runtime.h>
#include <cuda_bf16.h>
#include <cstdint>

// Problem: out[t, d] = code[weight[row, d]] * absmax[row],  row = tokens[t]
// Shapes: tokens [4*2048]=8192, weight [50400, 4096] int32 codes (0..255),
//         absmax [50400] (BLOCK==DIM==4096 -> one block per row), code [256].
// Output: [8192, 4096] fp32.
//
// Pure HBM-bound gather: ~134 MB read (codes) + ~134 MB write (fp32 out).

static constexpr int DIM = 4096;
static constexpr int THREADS = 256;
static constexpr int VEC_PER_THREAD = DIM / 4 / THREADS;  // 4 int4 loads per thread

__global__ __launch_bounds__(THREADS)
void bnb_embed_kernel(const int* __restrict__ tokens,
                      const int* __restrict__ weight,
                      const float* __restrict__ absmax,
                      const float* __restrict__ code,
                      float* __restrict__ out)
{
    __shared__ float s_code[256];
    const int tid = threadIdx.x;
    // Stage the 256-entry LUT into shared memory (1 KB).
    s_code[tid] = code[tid];
    __syncthreads();

    const int t = blockIdx.x;
    const int row = tokens[t];
    const float scale = __ldg(&absmax[row]);

    const int4* __restrict__ wrow =
        reinterpret_cast<const int4*>(weight + (long long)row * DIM);
    float4* __restrict__ orow =
        reinterpret_cast<float4*>(out + (long long)t * DIM);

#pragma unroll
    for (int i = 0; i < VEC_PER_THREAD; i++) {
        const int idx = tid + i * THREADS;   // coalesced 16B-per-lane accesses
        const int4 q = wrow[idx];
        float4 v;
        v.x = s_code[q.x] * scale;
        v.y = s_code[q.y] * scale;
        v.z = s_code[q.z] * scale;
        v.w = s_code[q.w] * scale;
        orow[idx] = v;
    }
}

extern "C" void kernel_launch(void* const* d_in, const int* in_sizes, int n_in,
                              void* d_out, int out_size)
{
    const int*   tokens = (const int*)d_in[0];    // [B*S] = 8192
    const int*   weight = (const int*)d_in[1];    // [50400*4096]
    const float* absmax = (const float*)d_in[2];  // [50400]
    const float* code   = (const float*)d_in[3];  // [256]
    float*       out    = (float*)d_out;          // [8192*4096]

    const int n_tokens = in_sizes[0];             // 8192
    bnb_embed_kernel<<<n_tokens, THREADS>>>(tokens, weight, absmax, code, out);
}